// round 4
// baseline (speedup 1.0000x reference)
#include <cuda_runtime.h>

// BilateralGrid apply: out = trilerp(grid, coords, luminance(pixels)) affine-applied to pixels.
// Grid: (16,16,8,12) f32 = 96KB -> cached in dynamic shared memory per CTA.
// Each thread processes a quad of 4 pixels for fully vectorized float4 streaming.

#define SH 16
#define SW 16
#define SL 8
#define GRID_F4   6144      // 16*16*8*12 floats / 4
#define NTHREADS  256
#define NBLOCKS   304       // ~2 CTAs per SM on 152-SM GB300
#define SMEM_BYTES (GRID_F4 * 16)   // 98304

__global__ __launch_bounds__(NTHREADS, 2)
void bilateral_grid_kernel(const float4* __restrict__ px4,
                           const float4* __restrict__ co4,
                           const float4* __restrict__ grid4,
                           float4* __restrict__ out4,
                           int nquad)
{
    extern __shared__ float4 sg[];

    // Cooperative load of the full grid into shared memory (24 float4 per thread).
    #pragma unroll 4
    for (int i = threadIdx.x; i < GRID_F4; i += NTHREADS)
        sg[i] = grid4[i];
    __syncthreads();

    const int stride = gridDim.x * blockDim.x;
    for (int q = blockIdx.x * blockDim.x + threadIdx.x; q < nquad; q += stride) {
        // ---- coalesced streaming loads: 4 pixels (12 floats) + 4 coords (8 floats) ----
        const float4 pa = px4[3 * q + 0];
        const float4 pb = px4[3 * q + 1];
        const float4 pc = px4[3 * q + 2];
        const float4 ca = co4[2 * q + 0];
        const float4 cb = co4[2 * q + 1];

        const float pr[4] = {pa.x, pa.w, pb.z, pc.y};
        const float pg[4] = {pa.y, pb.x, pb.w, pc.z};
        const float pbv[4] = {pa.z, pb.y, pc.x, pc.w};
        const float cx[4] = {ca.x, ca.z, cb.x, cb.z};
        const float cy[4] = {ca.y, ca.w, cb.y, cb.w};

        float o[12];

        #pragma unroll
        for (int k = 0; k < 4; k++) {
            const float r = pr[k], g = pg[k], b = pbv[k];

            // guide = luminance
            const float guide = 0.2126f * r + 0.7152f * g + 0.0722f * b;

            // grid coordinates with reference clamping
            const float gx = fminf(fmaxf(cx[k] * (float)(SW - 1), 0.0f), (float)SW - 1.001f);
            const float gy = fminf(fmaxf(cy[k] * (float)(SH - 1), 0.0f), (float)SH - 1.001f);
            const float gcl = fminf(fmaxf(guide, 0.0f), 1.0f);
            const float gz = fminf(fmaxf(gcl * (float)(SL - 1), 0.0f), (float)SL - 1.001f);

            const int x0 = (int)gx;
            const int y0 = (int)gy;
            const int z0 = (int)gz;
            const float fx = gx - (float)x0;
            const float fy = gy - (float)y0;
            const float fz = gz - (float)z0;

            // After clamping, x0<=14, y0<=14, z0<=6  => x1=x0+1 etc. always in-bounds.
            const float wx0 = 1.0f - fx, wx1 = fx;
            const float wy0 = 1.0f - fy, wy1 = fy;
            const float wz0 = 1.0f - fz, wz1 = fz;

            const float w000 = wy0 * wx0 * wz0;
            const float w001 = wy0 * wx0 * wz1;
            const float w010 = wy0 * wx1 * wz0;
            const float w011 = wy0 * wx1 * wz1;
            const float w100 = wy1 * wx0 * wz0;
            const float w101 = wy1 * wx0 * wz1;
            const float w110 = wy1 * wx1 * wz0;
            const float w111 = wy1 * wx1 * wz1;

            // corner linear id: ((y*16 + x)*8 + z), float4 offset = 3*id
            const int base = ((y0 << 4) + x0) * SL + z0;  // (y0*16+x0)*8+z0

            float4 a0 = make_float4(0.f, 0.f, 0.f, 0.f);
            float4 a1 = make_float4(0.f, 0.f, 0.f, 0.f);
            float4 a2 = make_float4(0.f, 0.f, 0.f, 0.f);

            const int offs[8] = {0, 1, SL, SL + 1,
                                 SW * SL, SW * SL + 1, SW * SL + SL, SW * SL + SL + 1};
            const float ws[8] = {w000, w001, w010, w011, w100, w101, w110, w111};

            #pragma unroll
            for (int cidx = 0; cidx < 8; cidx++) {
                const int gi = 3 * (base + offs[cidx]);
                const float w = ws[cidx];
                const float4 t0 = sg[gi + 0];
                const float4 t1 = sg[gi + 1];
                const float4 t2 = sg[gi + 2];
                a0.x = fmaf(w, t0.x, a0.x); a0.y = fmaf(w, t0.y, a0.y);
                a0.z = fmaf(w, t0.z, a0.z); a0.w = fmaf(w, t0.w, a0.w);
                a1.x = fmaf(w, t1.x, a1.x); a1.y = fmaf(w, t1.y, a1.y);
                a1.z = fmaf(w, t1.z, a1.z); a1.w = fmaf(w, t1.w, a1.w);
                a2.x = fmaf(w, t2.x, a2.x); a2.y = fmaf(w, t2.y, a2.y);
                a2.z = fmaf(w, t2.z, a2.z); a2.w = fmaf(w, t2.w, a2.w);
            }

            // affine apply: rows of A are (a0.xyzw), (a1.xyzw), (a2.xyzw)
            o[3 * k + 0] = fmaf(a0.x, r, fmaf(a0.y, g, fmaf(a0.z, b, a0.w)));
            o[3 * k + 1] = fmaf(a1.x, r, fmaf(a1.y, g, fmaf(a1.z, b, a1.w)));
            o[3 * k + 2] = fmaf(a2.x, r, fmaf(a2.y, g, fmaf(a2.z, b, a2.w)));
        }

        // ---- coalesced streaming stores: 12 floats -> 3 float4 ----
        out4[3 * q + 0] = make_float4(o[0], o[1], o[2], o[3]);
        out4[3 * q + 1] = make_float4(o[4], o[5], o[6], o[7]);
        out4[3 * q + 2] = make_float4(o[8], o[9], o[10], o[11]);
    }
}

extern "C" void kernel_launch(void* const* d_in, const int* in_sizes, int n_in,
                              void* d_out, int out_size)
{
    const float4* px4 = (const float4*)d_in[0];   // pixels (B,H,W,3) f32
    const float4* co4 = (const float4*)d_in[1];   // coords (B,H,W,2) f32
    const float4* gr4 = (const float4*)d_in[2];   // grid (16,16,8,12) f32
    float4* out4 = (float4*)d_out;

    const int N = in_sizes[0] / 3;   // number of pixels
    const int nquad = N / 4;         // N = 8294400, divisible by 4

    cudaFuncSetAttribute(bilateral_grid_kernel,
                         cudaFuncAttributeMaxDynamicSharedMemorySize, SMEM_BYTES);

    bilateral_grid_kernel<<<NBLOCKS, NTHREADS, SMEM_BYTES>>>(px4, co4, gr4, out4, nquad);
}

// round 9
// speedup vs baseline: 1.6121x; 1.6121x over previous
#include <cuda_runtime.h>
#include <cuda_fp16.h>

// BilateralGrid apply. Grid (16,16,8,12) f32 is converted to fp16 in shared
// memory (24B/cell, 48KB). Gather uses LDS.64 only (16 start-bank groups at
// 2-bank granularity -> far fewer conflicts than 48B-stride LDS.128).
// Accumulation is fp32; only storage is quantized.

#define SH 16
#define SW 16
#define SL 8
#define GRID_F4   6144            // 16*16*8*12 floats / 4
#define NTHREADS  256
#define NBLOCKS   304
#define SMEM_BYTES (16*16*8*24)   // 49152 bytes: 2048 cells * 12 halves

__global__ __launch_bounds__(NTHREADS, 2)
void bilateral_grid_kernel(const float4* __restrict__ px4,
                           const float4* __restrict__ co4,
                           const float4* __restrict__ grid4,
                           float4* __restrict__ out4,
                           int nquad)
{
    extern __shared__ uint2 sg[];   // 6144 uint2; uint2 = 4 packed halves

    // Cooperative fill: read grid as float4, pack to half4 (uint2).
    #pragma unroll 4
    for (int i = threadIdx.x; i < GRID_F4; i += NTHREADS) {
        const float4 v = grid4[i];
        const __half2 lo = __floats2half2_rn(v.x, v.y);
        const __half2 hi = __floats2half2_rn(v.z, v.w);
        uint2 u;
        u.x = *reinterpret_cast<const unsigned*>(&lo);
        u.y = *reinterpret_cast<const unsigned*>(&hi);
        sg[i] = u;
    }
    __syncthreads();

    const int stride = gridDim.x * blockDim.x;
    for (int q = blockIdx.x * blockDim.x + threadIdx.x; q < nquad; q += stride) {
        // ---- coalesced streaming loads: 4 pixels (12 floats) + 4 coords (8 floats) ----
        const float4 pa = px4[3 * q + 0];
        const float4 pb = px4[3 * q + 1];
        const float4 pc = px4[3 * q + 2];
        const float4 ca = co4[2 * q + 0];
        const float4 cb = co4[2 * q + 1];

        const float pr[4]  = {pa.x, pa.w, pb.z, pc.y};
        const float pg[4]  = {pa.y, pb.x, pb.w, pc.z};
        const float pbv[4] = {pa.z, pb.y, pc.x, pc.w};
        const float cx[4]  = {ca.x, ca.z, cb.x, cb.z};
        const float cy[4]  = {ca.y, ca.w, cb.y, cb.w};

        float o[12];

        #pragma unroll
        for (int k = 0; k < 4; k++) {
            const float r = pr[k], g = pg[k], b = pbv[k];

            const float guide = 0.2126f * r + 0.7152f * g + 0.0722f * b;

            const float gx  = fminf(fmaxf(cx[k] * (float)(SW - 1), 0.0f), (float)SW - 1.001f);
            const float gy  = fminf(fmaxf(cy[k] * (float)(SH - 1), 0.0f), (float)SH - 1.001f);
            const float gcl = fminf(fmaxf(guide, 0.0f), 1.0f);
            const float gz  = fminf(fmaxf(gcl * (float)(SL - 1), 0.0f), (float)SL - 1.001f);

            const int x0 = (int)gx;
            const int y0 = (int)gy;
            const int z0 = (int)gz;
            const float fx = gx - (float)x0;
            const float fy = gy - (float)y0;
            const float fz = gz - (float)z0;

            const float wx0 = 1.0f - fx, wx1 = fx;
            const float wy0 = 1.0f - fy, wy1 = fy;
            const float wz0 = 1.0f - fz, wz1 = fz;

            const float ws[8] = {wy0 * wx0 * wz0, wy0 * wx0 * wz1,
                                 wy0 * wx1 * wz0, wy0 * wx1 * wz1,
                                 wy1 * wx0 * wz0, wy1 * wx0 * wz1,
                                 wy1 * wx1 * wz0, wy1 * wx1 * wz1};

            // cell id: (y*16 + x)*8 + z  -> uint2 index 3*id (24B stride)
            const int base = ((y0 << 4) + x0) * SL + z0;
            const int offs[8] = {0, 1, SL, SL + 1,
                                 SW * SL, SW * SL + 1, SW * SL + SL, SW * SL + SL + 1};

            float A[12];
            #pragma unroll
            for (int j = 0; j < 12; j++) A[j] = 0.0f;

            #pragma unroll
            for (int cidx = 0; cidx < 8; cidx++) {
                const int gi = 3 * (base + offs[cidx]);
                const float w = ws[cidx];
                const uint2 u0 = sg[gi + 0];
                const uint2 u1 = sg[gi + 1];
                const uint2 u2 = sg[gi + 2];

                const float2 f0 = __half22float2(*reinterpret_cast<const __half2*>(&u0.x));
                const float2 f1 = __half22float2(*reinterpret_cast<const __half2*>(&u0.y));
                const float2 f2 = __half22float2(*reinterpret_cast<const __half2*>(&u1.x));
                const float2 f3 = __half22float2(*reinterpret_cast<const __half2*>(&u1.y));
                const float2 f4 = __half22float2(*reinterpret_cast<const __half2*>(&u2.x));
                const float2 f5 = __half22float2(*reinterpret_cast<const __half2*>(&u2.y));

                A[0]  = fmaf(w, f0.x, A[0]);  A[1]  = fmaf(w, f0.y, A[1]);
                A[2]  = fmaf(w, f1.x, A[2]);  A[3]  = fmaf(w, f1.y, A[3]);
                A[4]  = fmaf(w, f2.x, A[4]);  A[5]  = fmaf(w, f2.y, A[5]);
                A[6]  = fmaf(w, f3.x, A[6]);  A[7]  = fmaf(w, f3.y, A[7]);
                A[8]  = fmaf(w, f4.x, A[8]);  A[9]  = fmaf(w, f4.y, A[9]);
                A[10] = fmaf(w, f5.x, A[10]); A[11] = fmaf(w, f5.y, A[11]);
            }

            // affine rows: (A[0..3]), (A[4..7]), (A[8..11])
            o[3 * k + 0] = fmaf(A[0], r, fmaf(A[1],  g, fmaf(A[2],  b, A[3])));
            o[3 * k + 1] = fmaf(A[4], r, fmaf(A[5],  g, fmaf(A[6],  b, A[7])));
            o[3 * k + 2] = fmaf(A[8], r, fmaf(A[9],  g, fmaf(A[10], b, A[11])));
        }

        // ---- coalesced streaming stores: 12 floats -> 3 float4 ----
        out4[3 * q + 0] = make_float4(o[0], o[1], o[2],  o[3]);
        out4[3 * q + 1] = make_float4(o[4], o[5], o[6],  o[7]);
        out4[3 * q + 2] = make_float4(o[8], o[9], o[10], o[11]);
    }
}

extern "C" void kernel_launch(void* const* d_in, const int* in_sizes, int n_in,
                              void* d_out, int out_size)
{
    const float4* px4 = (const float4*)d_in[0];   // pixels (B,H,W,3) f32
    const float4* co4 = (const float4*)d_in[1];   // coords (B,H,W,2) f32
    const float4* gr4 = (const float4*)d_in[2];   // grid (16,16,8,12) f32
    float4* out4 = (float4*)d_out;

    const int N = in_sizes[0] / 3;   // number of pixels
    const int nquad = N / 4;         // 8294400 / 4

    cudaFuncSetAttribute(bilateral_grid_kernel,
                         cudaFuncAttributeMaxDynamicSharedMemorySize, SMEM_BYTES);

    bilateral_grid_kernel<<<NBLOCKS, NTHREADS, SMEM_BYTES>>>(px4, co4, gr4, out4, nquad);
}

// round 10
// speedup vs baseline: 1.9301x; 1.1972x over previous
#include <cuda_runtime.h>
#include <cuda_fp16.h>

// BilateralGrid apply. Grid (16,16,8,12) f32 -> z-pair replicated fp16 smem:
// for each zp in [0,7), (y,x): a 48B block of 12 half2 = {coef_j@z=zp, coef_j@z=zp+1}.
// Each (y,x) corner of the trilerp needs exactly 3 aligned LDS.128 (both z cells),
// i.e. 12 LDS.128 per pixel instead of 24 LDS.64 -> ~30% less smem crossbar work.

#define SH 16
#define SW 16
#define SL 8
#define NTHREADS  256
#define NBLOCKS   304
#define NPAIRS    7                       // z0 in 0..6
#define SMEM_U32  (NPAIRS * 256 * 12)     // 21504 half2 words
#define SMEM_BYTES (SMEM_U32 * 4)         // 86016 bytes

__global__ __launch_bounds__(NTHREADS, 2)
void bilateral_grid_kernel(const float4* __restrict__ px4,
                           const float4* __restrict__ co4,
                           const float* __restrict__ gridf,
                           float4* __restrict__ out4,
                           int nquad)
{
    extern __shared__ unsigned sgrid[];   // half2 per word; 16B-aligned base

    // ---- one-time fill: replicate grid into z-pair interleaved fp16 blocks ----
    // dst word index = blk*12 + j, blk = zp*256 + (y*16+x)
    // src: grid[(y*16+x)*8*12 + z*12 + j]
    #pragma unroll 4
    for (int idx = threadIdx.x; idx < SMEM_U32; idx += NTHREADS) {
        const int j   = idx % 12;
        const int blk = idx / 12;
        const int zp  = blk >> 8;
        const int yx  = blk & 255;
        const float a = gridf[(yx * SL + zp) * 12 + j];
        const float b = gridf[(yx * SL + zp + 1) * 12 + j];
        const __half2 h = __floats2half2_rn(a, b);
        sgrid[idx] = *reinterpret_cast<const unsigned*>(&h);
    }
    __syncthreads();

    const uint4* sg4 = reinterpret_cast<const uint4*>(sgrid);

    const int stride = gridDim.x * blockDim.x;
    for (int q = blockIdx.x * blockDim.x + threadIdx.x; q < nquad; q += stride) {
        // ---- coalesced streaming loads: 4 pixels (12 floats) + 4 coords (8 floats) ----
        const float4 pa = px4[3 * q + 0];
        const float4 pb = px4[3 * q + 1];
        const float4 pc = px4[3 * q + 2];
        const float4 ca = co4[2 * q + 0];
        const float4 cb = co4[2 * q + 1];

        const float pr[4]  = {pa.x, pa.w, pb.z, pc.y};
        const float pg[4]  = {pa.y, pb.x, pb.w, pc.z};
        const float pbv[4] = {pa.z, pb.y, pc.x, pc.w};
        const float cx[4]  = {ca.x, ca.z, cb.x, cb.z};
        const float cy[4]  = {ca.y, ca.w, cb.y, cb.w};

        float o[12];

        #pragma unroll
        for (int k = 0; k < 4; k++) {
            const float r = pr[k], g = pg[k], b = pbv[k];

            const float guide = 0.2126f * r + 0.7152f * g + 0.0722f * b;

            const float gx  = fminf(fmaxf(cx[k] * (float)(SW - 1), 0.0f), (float)SW - 1.001f);
            const float gy  = fminf(fmaxf(cy[k] * (float)(SH - 1), 0.0f), (float)SH - 1.001f);
            const float gcl = fminf(fmaxf(guide, 0.0f), 1.0f);
            const float gz  = fminf(fmaxf(gcl * (float)(SL - 1), 0.0f), (float)SL - 1.001f);

            const int x0 = (int)gx;
            const int y0 = (int)gy;
            const int z0 = (int)gz;
            const float fx = gx - (float)x0;
            const float fy = gy - (float)y0;
            const float fz = gz - (float)z0;

            const float wx0 = 1.0f - fx, wx1 = fx;
            const float wy0 = 1.0f - fy, wy1 = fy;

            // 4 (y,x) corner weights; z handled inside via fz lerp on half2 pairs
            const float wc[4] = {wy0 * wx0, wy0 * wx1, wy1 * wx0, wy1 * wx1};

            // block index: zp*256 + y*16 + x ; uint4 index = blk*3
            const int base = (z0 << 8) + (y0 << 4) + x0;
            const int coff[4] = {0, 1, SW, SW + 1};

            float A[12];
            #pragma unroll
            for (int j = 0; j < 12; j++) A[j] = 0.0f;

            #pragma unroll
            for (int c = 0; c < 4; c++) {
                const int bi = 3 * (base + coff[c]);
                const float w = wc[c];
                const uint4 u0 = sg4[bi + 0];   // coefs 0..3  (half2: lo=z0, hi=z1)
                const uint4 u1 = sg4[bi + 1];   // coefs 4..7
                const uint4 u2 = sg4[bi + 2];   // coefs 8..11
                const unsigned uu[12] = {u0.x, u0.y, u0.z, u0.w,
                                         u1.x, u1.y, u1.z, u1.w,
                                         u2.x, u2.y, u2.z, u2.w};
                #pragma unroll
                for (int j = 0; j < 12; j++) {
                    const float2 f = __half22float2(*reinterpret_cast<const __half2*>(&uu[j]));
                    const float v = fmaf(fz, f.y - f.x, f.x);   // z-lerp
                    A[j] = fmaf(w, v, A[j]);
                }
            }

            // affine rows: (A[0..3]), (A[4..7]), (A[8..11])
            o[3 * k + 0] = fmaf(A[0], r, fmaf(A[1],  g, fmaf(A[2],  b, A[3])));
            o[3 * k + 1] = fmaf(A[4], r, fmaf(A[5],  g, fmaf(A[6],  b, A[7])));
            o[3 * k + 2] = fmaf(A[8], r, fmaf(A[9],  g, fmaf(A[10], b, A[11])));
        }

        // ---- coalesced streaming stores: 12 floats -> 3 float4 ----
        out4[3 * q + 0] = make_float4(o[0], o[1], o[2],  o[3]);
        out4[3 * q + 1] = make_float4(o[4], o[5], o[6],  o[7]);
        out4[3 * q + 2] = make_float4(o[8], o[9], o[10], o[11]);
    }
}

extern "C" void kernel_launch(void* const* d_in, const int* in_sizes, int n_in,
                              void* d_out, int out_size)
{
    const float4* px4 = (const float4*)d_in[0];   // pixels (B,H,W,3) f32
    const float4* co4 = (const float4*)d_in[1];   // coords (B,H,W,2) f32
    const float*  grf = (const float*)d_in[2];    // grid (16,16,8,12) f32
    float4* out4 = (float4*)d_out;

    const int N = in_sizes[0] / 3;   // number of pixels
    const int nquad = N / 4;         // 8294400 / 4

    cudaFuncSetAttribute(bilateral_grid_kernel,
                         cudaFuncAttributeMaxDynamicSharedMemorySize, SMEM_BYTES);

    bilateral_grid_kernel<<<NBLOCKS, NTHREADS, SMEM_BYTES>>>(px4, co4, grf, out4, nquad);
}

// round 11
// speedup vs baseline: 1.9528x; 1.0118x over previous
#include <cuda_runtime.h>
#include <cuda_fp16.h>

// BilateralGrid apply. Grid (16,16,8,12) f32 -> z-pair replicated fp16 smem:
// for each zp in [0,7), (y,x): a 48B block of 12 half2 = {coef_j@z=zp, coef_j@z=zp+1}.
// Each (y,x) corner = 3 aligned LDS.128. Accumulation over the 4 (y,x) corners
// is done in fp16x2 (HFMA2) since fz is identical for all corners; only the
// final z-lerp is fp32. This cuts ~48 cvt + ~84 FFMA per pixel vs fp32 accum.

#define SH 16
#define SW 16
#define SL 8
#define NTHREADS  256
#define NBLOCKS   304
#define NPAIRS    7                       // z0 in 0..6
#define SMEM_U32  (NPAIRS * 256 * 12)     // 21504 half2 words
#define SMEM_BYTES (SMEM_U32 * 4)         // 86016 bytes

__global__ __launch_bounds__(NTHREADS, 2)
void bilateral_grid_kernel(const float4* __restrict__ px4,
                           const float4* __restrict__ co4,
                           const float* __restrict__ gridf,
                           float4* __restrict__ out4,
                           int nquad)
{
    extern __shared__ unsigned sgrid[];   // half2 per word; 16B-aligned base

    // ---- one-time fill: replicate grid into z-pair interleaved fp16 blocks ----
    // dst word index = blk*12 + j, blk = zp*256 + (y*16+x)
    // src: grid[(y*16+x)*8*12 + z*12 + j]
    #pragma unroll 4
    for (int idx = threadIdx.x; idx < SMEM_U32; idx += NTHREADS) {
        const int j   = idx % 12;
        const int blk = idx / 12;
        const int zp  = blk >> 8;
        const int yx  = blk & 255;
        const float a = gridf[(yx * SL + zp) * 12 + j];
        const float b = gridf[(yx * SL + zp + 1) * 12 + j];
        const __half2 h = __floats2half2_rn(a, b);
        sgrid[idx] = *reinterpret_cast<const unsigned*>(&h);
    }
    __syncthreads();

    const uint4* sg4 = reinterpret_cast<const uint4*>(sgrid);

    const int stride = gridDim.x * blockDim.x;
    for (int q = blockIdx.x * blockDim.x + threadIdx.x; q < nquad; q += stride) {
        // ---- coalesced streaming loads: 4 pixels (12 floats) + 4 coords (8 floats) ----
        const float4 pa = px4[3 * q + 0];
        const float4 pb = px4[3 * q + 1];
        const float4 pc = px4[3 * q + 2];
        const float4 ca = co4[2 * q + 0];
        const float4 cb = co4[2 * q + 1];

        const float pr[4]  = {pa.x, pa.w, pb.z, pc.y};
        const float pg[4]  = {pa.y, pb.x, pb.w, pc.z};
        const float pbv[4] = {pa.z, pb.y, pc.x, pc.w};
        const float cx[4]  = {ca.x, ca.z, cb.x, cb.z};
        const float cy[4]  = {ca.y, ca.w, cb.y, cb.w};

        float o[12];

        #pragma unroll
        for (int k = 0; k < 4; k++) {
            const float r = pr[k], g = pg[k], b = pbv[k];

            const float guide = 0.2126f * r + 0.7152f * g + 0.0722f * b;

            const float gx  = fminf(fmaxf(cx[k] * (float)(SW - 1), 0.0f), (float)SW - 1.001f);
            const float gy  = fminf(fmaxf(cy[k] * (float)(SH - 1), 0.0f), (float)SH - 1.001f);
            const float gcl = fminf(fmaxf(guide, 0.0f), 1.0f);
            const float gz  = fminf(fmaxf(gcl * (float)(SL - 1), 0.0f), (float)SL - 1.001f);

            const int x0 = (int)gx;
            const int y0 = (int)gy;
            const int z0 = (int)gz;
            const float fx = gx - (float)x0;
            const float fy = gy - (float)y0;
            const float fz = gz - (float)z0;

            const float wx0 = 1.0f - fx, wx1 = fx;
            const float wy0 = 1.0f - fy, wy1 = fy;

            // 4 (y,x) corner weights as broadcast half2; z handled at the end
            const __half2 wc[4] = {__float2half2_rn(wy0 * wx0),
                                   __float2half2_rn(wy0 * wx1),
                                   __float2half2_rn(wy1 * wx0),
                                   __float2half2_rn(wy1 * wx1)};

            // block index: zp*256 + y*16 + x ; uint4 index = blk*3
            const int base = (z0 << 8) + (y0 << 4) + x0;
            const int coff[4] = {0, 1, SW, SW + 1};

            __half2 acc[12];
            #pragma unroll
            for (int j = 0; j < 12; j++) acc[j] = __float2half2_rn(0.0f);

            #pragma unroll
            for (int c = 0; c < 4; c++) {
                const int bi = 3 * (base + coff[c]);
                const __half2 w2 = wc[c];
                const uint4 u0 = sg4[bi + 0];   // coefs 0..3  (half2: lo=z0, hi=z1)
                const uint4 u1 = sg4[bi + 1];   // coefs 4..7
                const uint4 u2 = sg4[bi + 2];   // coefs 8..11

                acc[0]  = __hfma2(w2, *reinterpret_cast<const __half2*>(&u0.x), acc[0]);
                acc[1]  = __hfma2(w2, *reinterpret_cast<const __half2*>(&u0.y), acc[1]);
                acc[2]  = __hfma2(w2, *reinterpret_cast<const __half2*>(&u0.z), acc[2]);
                acc[3]  = __hfma2(w2, *reinterpret_cast<const __half2*>(&u0.w), acc[3]);
                acc[4]  = __hfma2(w2, *reinterpret_cast<const __half2*>(&u1.x), acc[4]);
                acc[5]  = __hfma2(w2, *reinterpret_cast<const __half2*>(&u1.y), acc[5]);
                acc[6]  = __hfma2(w2, *reinterpret_cast<const __half2*>(&u1.z), acc[6]);
                acc[7]  = __hfma2(w2, *reinterpret_cast<const __half2*>(&u1.w), acc[7]);
                acc[8]  = __hfma2(w2, *reinterpret_cast<const __half2*>(&u2.x), acc[8]);
                acc[9]  = __hfma2(w2, *reinterpret_cast<const __half2*>(&u2.y), acc[9]);
                acc[10] = __hfma2(w2, *reinterpret_cast<const __half2*>(&u2.z), acc[10]);
                acc[11] = __hfma2(w2, *reinterpret_cast<const __half2*>(&u2.w), acc[11]);
            }

            // final fp32 z-lerp per coefficient
            float A[12];
            #pragma unroll
            for (int j = 0; j < 12; j++) {
                const float2 f = __half22float2(acc[j]);
                A[j] = fmaf(fz, f.y - f.x, f.x);
            }

            // affine rows: (A[0..3]), (A[4..7]), (A[8..11])
            o[3 * k + 0] = fmaf(A[0], r, fmaf(A[1],  g, fmaf(A[2],  b, A[3])));
            o[3 * k + 1] = fmaf(A[4], r, fmaf(A[5],  g, fmaf(A[6],  b, A[7])));
            o[3 * k + 2] = fmaf(A[8], r, fmaf(A[9],  g, fmaf(A[10], b, A[11])));
        }

        // ---- coalesced streaming stores: 12 floats -> 3 float4 ----
        out4[3 * q + 0] = make_float4(o[0], o[1], o[2],  o[3]);
        out4[3 * q + 1] = make_float4(o[4], o[5], o[6],  o[7]);
        out4[3 * q + 2] = make_float4(o[8], o[9], o[10], o[11]);
    }
}

extern "C" void kernel_launch(void* const* d_in, const int* in_sizes, int n_in,
                              void* d_out, int out_size)
{
    const float4* px4 = (const float4*)d_in[0];   // pixels (B,H,W,3) f32
    const float4* co4 = (const float4*)d_in[1];   // coords (B,H,W,2) f32
    const float*  grf = (const float*)d_in[2];    // grid (16,16,8,12) f32
    float4* out4 = (float4*)d_out;

    const int N = in_sizes[0] / 3;   // number of pixels
    const int nquad = N / 4;         // 8294400 / 4

    cudaFuncSetAttribute(bilateral_grid_kernel,
                         cudaFuncAttributeMaxDynamicSharedMemorySize, SMEM_BYTES);

    bilateral_grid_kernel<<<NBLOCKS, NTHREADS, SMEM_BYTES>>>(px4, co4, grf, out4, nquad);
}

// round 12
// speedup vs baseline: 2.0092x; 1.0289x over previous
#include <cuda_runtime.h>
#include <cuda_fp16.h>

// BilateralGrid apply. Grid (16,16,8,12) f32 -> z-pair replicated fp16 smem:
// for each zp in [0,7), (y,x): a 48B block of 12 half2 = {coef_j@z=zp, coef_j@z=zp+1}.
// Each (y,x) corner = 3 aligned LDS.128; HFMA2 accumulation over the 4 corners;
// final z-lerp in fp32. This round: 384 threads x 2 CTAs/SM (24 warps, occ 37.5%)
// to push the smem crossbar from 89.7% busy toward saturation.

#define SH 16
#define SW 16
#define SL 8
#define NTHREADS  384
#define NBLOCKS   304
#define NPAIRS    7                       // z0 in 0..6
#define SMEM_U32  (NPAIRS * 256 * 12)     // 21504 half2 words
#define SMEM_BYTES (SMEM_U32 * 4)         // 86016 bytes

__global__ __launch_bounds__(NTHREADS, 2)
void bilateral_grid_kernel(const float4* __restrict__ px4,
                           const float4* __restrict__ co4,
                           const float* __restrict__ gridf,
                           float4* __restrict__ out4,
                           int nquad)
{
    extern __shared__ unsigned sgrid[];   // half2 per word; 16B-aligned base

    // ---- one-time fill: replicate grid into z-pair interleaved fp16 blocks ----
    // dst word index = blk*12 + j, blk = zp*256 + (y*16+x)
    // src: grid[(y*16+x)*8*12 + z*12 + j]
    #pragma unroll 4
    for (int idx = threadIdx.x; idx < SMEM_U32; idx += NTHREADS) {
        const int j   = idx % 12;
        const int blk = idx / 12;
        const int zp  = blk >> 8;
        const int yx  = blk & 255;
        const float a = gridf[(yx * SL + zp) * 12 + j];
        const float b = gridf[(yx * SL + zp + 1) * 12 + j];
        const __half2 h = __floats2half2_rn(a, b);
        sgrid[idx] = *reinterpret_cast<const unsigned*>(&h);
    }
    __syncthreads();

    const uint4* sg4 = reinterpret_cast<const uint4*>(sgrid);

    const int stride = gridDim.x * blockDim.x;
    for (int q = blockIdx.x * blockDim.x + threadIdx.x; q < nquad; q += stride) {
        // ---- coalesced streaming loads: 4 pixels (12 floats) + 4 coords (8 floats) ----
        const float4 pa = px4[3 * q + 0];
        const float4 pb = px4[3 * q + 1];
        const float4 pc = px4[3 * q + 2];
        const float4 ca = co4[2 * q + 0];
        const float4 cb = co4[2 * q + 1];

        const float pr[4]  = {pa.x, pa.w, pb.z, pc.y};
        const float pg[4]  = {pa.y, pb.x, pb.w, pc.z};
        const float pbv[4] = {pa.z, pb.y, pc.x, pc.w};
        const float cx[4]  = {ca.x, ca.z, cb.x, cb.z};
        const float cy[4]  = {ca.y, ca.w, cb.y, cb.w};

        float o[12];

        #pragma unroll
        for (int k = 0; k < 4; k++) {
            const float r = pr[k], g = pg[k], b = pbv[k];

            const float guide = 0.2126f * r + 0.7152f * g + 0.0722f * b;

            const float gx  = fminf(fmaxf(cx[k] * (float)(SW - 1), 0.0f), (float)SW - 1.001f);
            const float gy  = fminf(fmaxf(cy[k] * (float)(SH - 1), 0.0f), (float)SH - 1.001f);
            const float gcl = fminf(fmaxf(guide, 0.0f), 1.0f);
            const float gz  = fminf(fmaxf(gcl * (float)(SL - 1), 0.0f), (float)SL - 1.001f);

            const int x0 = (int)gx;
            const int y0 = (int)gy;
            const int z0 = (int)gz;
            const float fx = gx - (float)x0;
            const float fy = gy - (float)y0;
            const float fz = gz - (float)z0;

            const float wx0 = 1.0f - fx, wx1 = fx;
            const float wy0 = 1.0f - fy, wy1 = fy;

            // 4 (y,x) corner weights as broadcast half2; z handled at the end
            const __half2 wc[4] = {__float2half2_rn(wy0 * wx0),
                                   __float2half2_rn(wy0 * wx1),
                                   __float2half2_rn(wy1 * wx0),
                                   __float2half2_rn(wy1 * wx1)};

            // block index: zp*256 + y*16 + x ; uint4 index = blk*3
            const int base = (z0 << 8) + (y0 << 4) + x0;
            const int coff[4] = {0, 1, SW, SW + 1};

            __half2 acc[12];
            #pragma unroll
            for (int j = 0; j < 12; j++) acc[j] = __float2half2_rn(0.0f);

            #pragma unroll
            for (int c = 0; c < 4; c++) {
                const int bi = 3 * (base + coff[c]);
                const __half2 w2 = wc[c];
                const uint4 u0 = sg4[bi + 0];   // coefs 0..3  (half2: lo=z0, hi=z1)
                const uint4 u1 = sg4[bi + 1];   // coefs 4..7
                const uint4 u2 = sg4[bi + 2];   // coefs 8..11

                acc[0]  = __hfma2(w2, *reinterpret_cast<const __half2*>(&u0.x), acc[0]);
                acc[1]  = __hfma2(w2, *reinterpret_cast<const __half2*>(&u0.y), acc[1]);
                acc[2]  = __hfma2(w2, *reinterpret_cast<const __half2*>(&u0.z), acc[2]);
                acc[3]  = __hfma2(w2, *reinterpret_cast<const __half2*>(&u0.w), acc[3]);
                acc[4]  = __hfma2(w2, *reinterpret_cast<const __half2*>(&u1.x), acc[4]);
                acc[5]  = __hfma2(w2, *reinterpret_cast<const __half2*>(&u1.y), acc[5]);
                acc[6]  = __hfma2(w2, *reinterpret_cast<const __half2*>(&u1.z), acc[6]);
                acc[7]  = __hfma2(w2, *reinterpret_cast<const __half2*>(&u1.w), acc[7]);
                acc[8]  = __hfma2(w2, *reinterpret_cast<const __half2*>(&u2.x), acc[8]);
                acc[9]  = __hfma2(w2, *reinterpret_cast<const __half2*>(&u2.y), acc[9]);
                acc[10] = __hfma2(w2, *reinterpret_cast<const __half2*>(&u2.z), acc[10]);
                acc[11] = __hfma2(w2, *reinterpret_cast<const __half2*>(&u2.w), acc[11]);
            }

            // final fp32 z-lerp per coefficient
            float A[12];
            #pragma unroll
            for (int j = 0; j < 12; j++) {
                const float2 f = __half22float2(acc[j]);
                A[j] = fmaf(fz, f.y - f.x, f.x);
            }

            // affine rows: (A[0..3]), (A[4..7]), (A[8..11])
            o[3 * k + 0] = fmaf(A[0], r, fmaf(A[1],  g, fmaf(A[2],  b, A[3])));
            o[3 * k + 1] = fmaf(A[4], r, fmaf(A[5],  g, fmaf(A[6],  b, A[7])));
            o[3 * k + 2] = fmaf(A[8], r, fmaf(A[9],  g, fmaf(A[10], b, A[11])));
        }

        // ---- coalesced streaming stores: 12 floats -> 3 float4 ----
        out4[3 * q + 0] = make_float4(o[0], o[1], o[2],  o[3]);
        out4[3 * q + 1] = make_float4(o[4], o[5], o[6],  o[7]);
        out4[3 * q + 2] = make_float4(o[8], o[9], o[10], o[11]);
    }
}

extern "C" void kernel_launch(void* const* d_in, const int* in_sizes, int n_in,
                              void* d_out, int out_size)
{
    const float4* px4 = (const float4*)d_in[0];   // pixels (B,H,W,3) f32
    const float4* co4 = (const float4*)d_in[1];   // coords (B,H,W,2) f32
    const float*  grf = (const float*)d_in[2];    // grid (16,16,8,12) f32
    float4* out4 = (float4*)d_out;

    const int N = in_sizes[0] / 3;   // number of pixels
    const int nquad = N / 4;         // 8294400 / 4

    cudaFuncSetAttribute(bilateral_grid_kernel,
                         cudaFuncAttributeMaxDynamicSharedMemorySize, SMEM_BYTES);

    bilateral_grid_kernel<<<NBLOCKS, NTHREADS, SMEM_BYTES>>>(px4, co4, grf, out4, nquad);
}